// round 2
// baseline (speedup 1.0000x reference)
#include <cuda_runtime.h>
#include <math.h>

#define HW 16384           // 128*128
#define CH 256
#define B_SZ 4
#define IMG_W 128
#define EPS 1e-5f

// ---------------- scratch (device globals; no allocation allowed) ----------------
// layout (float offsets):
//   P     : 0          size 16,777,216   (in_proj out)
//   XN    : 16777216   size 16,777,216   (layernorm out)
//   QKV   : 33554432   size 50,331,648
//   AO    : 83886080   size 16,777,216   (attention out)
//   AM    : 100663296  size 16,777,216   (proj out)
//   T     : 117440512  size 16,777,216   (o*tanh(cnext))
//   GATES : 134217728  size 67,108,864
__device__ __align__(256) float g_buf[201326592];
__device__ __align__(256) float g_red1[64];
__device__ __align__(256) float g_red2[64];
__device__ __align__(256) float g_scale1[1024];
__device__ __align__(256) float g_shift1[1024];
__device__ __align__(256) float g_scale2[1024];
__device__ __align__(256) float g_shift2[1024];

#define OFF_P     ((size_t)0)
#define OFF_XN    ((size_t)16777216)
#define OFF_QKV   ((size_t)33554432)
#define OFF_AO    ((size_t)83886080)
#define OFF_AM    ((size_t)100663296)
#define OFF_T     ((size_t)117440512)
#define OFF_GATES ((size_t)134217728)

// ---------------- utility: zero reduction buffers ----------------
__global__ void zero_red_kernel() {
    int i = threadIdx.x;
    if (i < 64) { g_red1[i] = 0.f; g_red2[i] = 0.f; }
}

// ---------------- generic SGEMM: Y[b] = W(MxK) @ X(K x HW) + bias ----------------
// MODE 0: X split (x: 64 ch, h: 256 ch)  [in_proj]
// MODE 1: plain X0 at b*K*HW             [qkv, proj]
// MODE 2: plain X0 with per-(b,k) affine (GroupNorm fused) [gates]
#define BM 128
#define BN 128
#define BK 8

template<int MODE>
__global__ void __launch_bounds__(256) gemm_k(
    const float* __restrict__ Wt, const float* __restrict__ bias,
    const float* __restrict__ X0, const float* __restrict__ X1,
    const float* __restrict__ scl, const float* __restrict__ shf,
    float* __restrict__ Y, int M, int K)
{
    const int b  = blockIdx.z;
    const int m0 = blockIdx.y * BM;
    const int n0 = blockIdx.x * BN;
    const int tid = threadIdx.x;

    __shared__ float As[2][BK][BM];
    __shared__ float Bs[2][BK][BN];

    const int a_m = tid >> 1;
    const int a_k = (tid & 1) << 2;
    const int b_k = tid >> 5;
    const int b_n = (tid & 31) << 2;
    const int tr  = tid >> 4;
    const int tc  = tid & 15;

    const float* Aptr = Wt + (size_t)(m0 + a_m) * K + a_k;

    float acc[8][8];
    #pragma unroll
    for (int i = 0; i < 8; i++)
        #pragma unroll
        for (int j = 0; j < 8; j++) acc[i][j] = 0.f;

    float4 aReg, bReg;

    // ---- prologue: fetch tile 0 ----
    aReg = *(const float4*)(Aptr);
    {
        int kk = b_k;
        const float* src;
        if (MODE == 0) {
            src = (kk < 64) ? (X0 + ((size_t)b * 64 + kk) * HW)
                            : (X1 + ((size_t)b * 256 + (kk - 64)) * HW);
        } else {
            src = X0 + ((size_t)b * K + kk) * HW;
        }
        bReg = *(const float4*)(src + n0 + b_n);
        if (MODE == 2) {
            float s2 = scl[b * K + kk], h2 = shf[b * K + kk];
            bReg.x = bReg.x * s2 + h2; bReg.y = bReg.y * s2 + h2;
            bReg.z = bReg.z * s2 + h2; bReg.w = bReg.w * s2 + h2;
        }
    }
    As[0][a_k + 0][a_m] = aReg.x; As[0][a_k + 1][a_m] = aReg.y;
    As[0][a_k + 2][a_m] = aReg.z; As[0][a_k + 3][a_m] = aReg.w;
    *(float4*)&Bs[0][b_k][b_n] = bReg;
    __syncthreads();

    const int nk = K / BK;
    for (int kt = 0; kt < nk; kt++) {
        const int cur = kt & 1;
        const bool more = (kt + 1 < nk);
        if (more) {
            int k0 = (kt + 1) * BK;
            aReg = *(const float4*)(Aptr + k0);
            int kk = k0 + b_k;
            const float* src;
            if (MODE == 0) {
                src = (kk < 64) ? (X0 + ((size_t)b * 64 + kk) * HW)
                                : (X1 + ((size_t)b * 256 + (kk - 64)) * HW);
            } else {
                src = X0 + ((size_t)b * K + kk) * HW;
            }
            bReg = *(const float4*)(src + n0 + b_n);
            if (MODE == 2) {
                float s2 = scl[b * K + kk], h2 = shf[b * K + kk];
                bReg.x = bReg.x * s2 + h2; bReg.y = bReg.y * s2 + h2;
                bReg.z = bReg.z * s2 + h2; bReg.w = bReg.w * s2 + h2;
            }
        }
        #pragma unroll
        for (int kk = 0; kk < BK; kk++) {
            float af[8], bf[8];
            *(float4*)(af)     = *(const float4*)&As[cur][kk][tr * 8];
            *(float4*)(af + 4) = *(const float4*)&As[cur][kk][tr * 8 + 4];
            *(float4*)(bf)     = *(const float4*)&Bs[cur][kk][tc * 8];
            *(float4*)(bf + 4) = *(const float4*)&Bs[cur][kk][tc * 8 + 4];
            #pragma unroll
            for (int i = 0; i < 8; i++)
                #pragma unroll
                for (int j = 0; j < 8; j++)
                    acc[i][j] = fmaf(af[i], bf[j], acc[i][j]);
        }
        if (more) {
            const int nxt = cur ^ 1;
            As[nxt][a_k + 0][a_m] = aReg.x; As[nxt][a_k + 1][a_m] = aReg.y;
            As[nxt][a_k + 2][a_m] = aReg.z; As[nxt][a_k + 3][a_m] = aReg.w;
            *(float4*)&Bs[nxt][b_k][b_n] = bReg;
        }
        __syncthreads();
    }

    #pragma unroll
    for (int i = 0; i < 8; i++) {
        int m = m0 + tr * 8 + i;
        float bi = bias[m];
        float* dst = Y + ((size_t)b * M + m) * HW + n0 + tc * 8;
        float4 r0 = make_float4(acc[i][0] + bi, acc[i][1] + bi, acc[i][2] + bi, acc[i][3] + bi);
        float4 r1 = make_float4(acc[i][4] + bi, acc[i][5] + bi, acc[i][6] + bi, acc[i][7] + bi);
        *(float4*)(dst) = r0;
        *(float4*)(dst + 4) = r1;
    }
}

// ---------------- per-pixel LayerNorm over 256 channels ----------------
__global__ void __launch_bounds__(256) ln_kernel(
    const float* __restrict__ P, const float* __restrict__ g,
    const float* __restrict__ be, float* __restrict__ XN)
{
    int idx = blockIdx.x * 256 + threadIdx.x;   // pixel over B*HW = 65536
    int b = idx >> 14;
    int p = idx & 16383;
    const float* base = P + (size_t)b * 256 * HW + p;
    float s = 0.f, ss = 0.f;
    for (int c = 0; c < 256; c++) {
        float v = base[(size_t)c * HW];
        s += v; ss += v * v;
    }
    float mu = s * (1.f / 256.f);
    float var = ss * (1.f / 256.f) - mu * mu;
    float rstd = rsqrtf(var + EPS);
    float* ob = XN + (size_t)b * 256 * HW + p;
    for (int c = 0; c < 256; c++) {
        float v = base[(size_t)c * HW];
        ob[(size_t)c * HW] = (v - mu) * rstd * __ldg(&g[c]) + __ldg(&be[c]);
    }
}

// ---------------- window attention (4x4 windows, 8 heads, hd=32) ----------------
// one block per window, 128 threads = 8 heads x 16 query tokens
__global__ void __launch_bounds__(128) attn_kernel(
    const float* __restrict__ QKV, float* __restrict__ AO)
{
    __shared__ float sq[8 * 512];   // [h][d][t], t fastest
    __shared__ float sk[8 * 512];
    __shared__ float sv[8 * 512];

    const int wc = blockIdx.x, wr = blockIdx.y, b = blockIdx.z;
    const int tid = threadIdx.x;
    const float* base = QKV + (size_t)b * 768 * HW;

    for (int e = tid; e < 3 * 4096; e += 128) {
        int t  = e & 15;
        int d  = (e >> 4) & 31;
        int hh = (e >> 9) & 7;
        int s  = e >> 12;
        int pix = (wr * 4 + (t >> 2)) * IMG_W + wc * 4 + (t & 3);
        float v = base[((size_t)(s * 256 + hh * 32 + d)) * HW + pix];
        float* sm = (s == 0) ? sq : (s == 1) ? sk : sv;
        sm[hh * 512 + d * 16 + t] = v;
    }
    __syncthreads();

    const int h  = tid >> 4;
    const int qt = tid & 15;
    const float* qb = sq + h * 512;
    const float* kb = sk + h * 512;
    const float* vb = sv + h * 512;

    float s[16];
    #pragma unroll
    for (int kt = 0; kt < 16; kt++) s[kt] = 0.f;
    #pragma unroll 4
    for (int d = 0; d < 32; d++) {
        float qv = qb[d * 16 + qt];
        #pragma unroll
        for (int kt = 0; kt < 16; kt++)
            s[kt] = fmaf(qv, kb[d * 16 + kt], s[kt]);
    }
    const float sc = 0.17677669529663687f;  // 1/sqrt(32)
    float mx = -1e30f;
    #pragma unroll
    for (int kt = 0; kt < 16; kt++) { s[kt] *= sc; mx = fmaxf(mx, s[kt]); }
    float den = 0.f;
    #pragma unroll
    for (int kt = 0; kt < 16; kt++) { s[kt] = __expf(s[kt] - mx); den += s[kt]; }
    float rden = 1.f / den;

    int pix = (wr * 4 + (qt >> 2)) * IMG_W + wc * 4 + (qt & 3);
    float* ob = AO + (size_t)b * 256 * HW + pix;
    #pragma unroll 4
    for (int d = 0; d < 32; d++) {
        float o = 0.f;
        #pragma unroll
        for (int kt = 0; kt < 16; kt++)
            o = fmaf(s[kt], vb[d * 16 + kt], o);
        ob[(size_t)(h * 32 + d) * HW] = o * rden;
    }
}

// ---------------- block reduction helper ----------------
__device__ __forceinline__ void block_sum2(float& s, float& ss) {
    __shared__ float sm1[8], sm2[8];
    #pragma unroll
    for (int o = 16; o > 0; o >>= 1) {
        s  += __shfl_xor_sync(0xffffffff, s, o);
        ss += __shfl_xor_sync(0xffffffff, ss, o);
    }
    int w = threadIdx.x >> 5, l = threadIdx.x & 31;
    if (l == 0) { sm1[w] = s; sm2[w] = ss; }
    __syncthreads();
    if (threadIdx.x < 32) {
        s  = (l < 8) ? sm1[l] : 0.f;
        ss = (l < 8) ? sm2[l] : 0.f;
        #pragma unroll
        for (int o = 4; o > 0; o >>= 1) {
            s  += __shfl_xor_sync(0xffffffff, s, o);
            ss += __shfl_xor_sync(0xffffffff, ss, o);
        }
    }
}

// ---------------- GroupNorm stage 1: reduce am ----------------
__global__ void __launch_bounds__(256) gn_reduce_kernel(const float* __restrict__ X) {
    int grp = blockIdx.y;                           // b*8+g, 0..31
    const float* base = X + (size_t)grp * 32 * HW;  // group is 524288 contiguous floats
    int start = blockIdx.x * 32768 + threadIdx.x;
    float s = 0.f, ss = 0.f;
    #pragma unroll 4
    for (int i = 0; i < 128; i++) {
        float v = base[start + i * 256];
        s += v; ss += v * v;
    }
    block_sum2(s, ss);
    if (threadIdx.x == 0) {
        atomicAdd(&g_red1[grp * 2 + 0], s);
        atomicAdd(&g_red1[grp * 2 + 1], ss);
    }
}

// ---------------- GroupNorm finalize: per-(b,c) scale/shift ----------------
__global__ void gn_finalize_kernel(const float* __restrict__ red,
                                   const float* __restrict__ g, const float* __restrict__ be,
                                   float* __restrict__ scale, float* __restrict__ shift)
{
    int i = blockIdx.x * 256 + threadIdx.x;   // b*256+c, 0..1023
    int c = i & 255;
    int grp = (i >> 8) * 8 + (c >> 5);
    const float invN = 1.f / 524288.f;
    float mu = red[grp * 2 + 0] * invN;
    float var = red[grp * 2 + 1] * invN - mu * mu;
    float rstd = rsqrtf(var + EPS);
    float gg = g[c];
    scale[i] = gg * rstd;
    shift[i] = be[c] - mu * rstd * gg;
}

// ---------------- LSTM elementwise + stats for second GroupNorm ----------------
__global__ void __launch_bounds__(256) lstm_kernel(
    const float* __restrict__ G, const float* __restrict__ Cin,
    float* __restrict__ Cout, float* __restrict__ T)
{
    size_t idx = (size_t)blockIdx.x * 256 + threadIdx.x;   // 0..16777215
    int b = (int)(idx >> 22);
    int rem = (int)(idx & 4194303);
    int c = rem >> 14;
    size_t gbase = (size_t)b * 1024 * HW + rem;

    float i_ = G[gbase];
    float f_ = G[gbase + (size_t)256 * HW];
    float o_ = G[gbase + (size_t)512 * HW];
    float g_ = G[gbase + (size_t)768 * HW];
    i_ = 1.f / (1.f + __expf(-i_));
    f_ = 1.f / (1.f + __expf(-f_));
    o_ = 1.f / (1.f + __expf(-o_));
    g_ = tanhf(g_);
    float cn = f_ * Cin[idx] + i_ * g_;
    Cout[idx] = cn;
    float t = o_ * tanhf(cn);
    T[idx] = t;

    float s = t, ss = t * t;
    block_sum2(s, ss);
    if (threadIdx.x == 0) {
        int grp = b * 8 + (c >> 5);
        atomicAdd(&g_red2[grp * 2 + 0], s);
        atomicAdd(&g_red2[grp * 2 + 1], ss);
    }
}

// ---------------- final: hnext = GroupNorm(t) ----------------
__global__ void __launch_bounds__(256) hnext_kernel(
    const float* __restrict__ T, const float* __restrict__ scale,
    const float* __restrict__ shift, float* __restrict__ Hout)
{
    size_t idx = (size_t)blockIdx.x * 256 + threadIdx.x;
    int b = (int)(idx >> 22);
    int c = (int)((idx >> 14) & 255);
    int sidx = b * 256 + c;
    Hout[idx] = T[idx] * __ldg(&scale[sidx]) + __ldg(&shift[sidx]);
}

// ---------------- launcher ----------------
extern "C" void kernel_launch(void* const* d_in, const int* in_sizes, int n_in,
                              void* d_out, int out_size)
{
    const float* x         = (const float*)d_in[0];
    const float* h         = (const float*)d_in[1];
    const float* c         = (const float*)d_in[2];
    const float* in_proj_w = (const float*)d_in[3];
    const float* in_proj_b = (const float*)d_in[4];
    const float* ln_g      = (const float*)d_in[5];
    const float* ln_b      = (const float*)d_in[6];
    const float* qkv_w     = (const float*)d_in[7];
    const float* qkv_b     = (const float*)d_in[8];
    const float* proj_w    = (const float*)d_in[9];
    const float* proj_b    = (const float*)d_in[10];
    const float* gates_w   = (const float*)d_in[11];
    const float* gates_b   = (const float*)d_in[12];
    const float* gn_g      = (const float*)d_in[13];
    const float* gn_b      = (const float*)d_in[14];
    float* out = (float*)d_out;

    float *buf, *red1, *red2, *sc1, *sh1, *sc2, *sh2;
    cudaGetSymbolAddress((void**)&buf,  g_buf);
    cudaGetSymbolAddress((void**)&red1, g_red1);
    cudaGetSymbolAddress((void**)&red2, g_red2);
    cudaGetSymbolAddress((void**)&sc1,  g_scale1);
    cudaGetSymbolAddress((void**)&sh1,  g_shift1);
    cudaGetSymbolAddress((void**)&sc2,  g_scale2);
    cudaGetSymbolAddress((void**)&sh2,  g_shift2);

    float* P     = buf + OFF_P;
    float* XN    = buf + OFF_XN;
    float* QKV   = buf + OFF_QKV;
    float* AO    = buf + OFF_AO;
    float* AM    = buf + OFF_AM;
    float* T     = buf + OFF_T;
    float* GATES = buf + OFF_GATES;

    // 0) zero reduction accumulators
    zero_red_kernel<<<1, 64>>>();

    // 1) in_proj: P = in_proj_w(256x320) @ [x;h] + b
    gemm_k<0><<<dim3(HW / BN, 256 / BM, B_SZ), 256>>>(
        in_proj_w, in_proj_b, x, h, nullptr, nullptr, P, 256, 320);

    // 2) LayerNorm per pixel
    ln_kernel<<<(B_SZ * HW) / 256, 256>>>(P, ln_g, ln_b, XN);

    // 3) qkv: QKV = qkv_w(768x256) @ XN + b
    gemm_k<1><<<dim3(HW / BN, 768 / BM, B_SZ), 256>>>(
        qkv_w, qkv_b, XN, nullptr, nullptr, nullptr, QKV, 768, 256);

    // 4) window attention -> AO
    attn_kernel<<<dim3(32, 32, B_SZ), 128>>>(QKV, AO);

    // 5) proj: AM = proj_w(256x256) @ AO + b
    gemm_k<1><<<dim3(HW / BN, 256 / BM, B_SZ), 256>>>(
        proj_w, proj_b, AO, nullptr, nullptr, nullptr, AM, 256, 256);

    // 6) GroupNorm(am) stats -> scale1/shift1
    gn_reduce_kernel<<<dim3(16, 32), 256>>>(AM);
    gn_finalize_kernel<<<4, 256>>>(red1, gn_g, gn_b, sc1, sh1);

    // 7) gates: GATES = gates_w(1024x256) @ GN(AM) + b  (GN fused via affine)
    gemm_k<2><<<dim3(HW / BN, 1024 / BM, B_SZ), 256>>>(
        gates_w, gates_b, AM, nullptr, sc1, sh1, GATES, 1024, 256);

    // 8) LSTM elementwise: cnext -> out[second half], t -> T, stats -> red2
    lstm_kernel<<<(B_SZ * 256 * HW) / 256, 256>>>(
        GATES, c, out + (size_t)B_SZ * 256 * HW, T);

    // 9) GroupNorm(t) -> hnext -> out[first half]
    gn_finalize_kernel<<<4, 256>>>(red2, gn_g, gn_b, sc2, sh2);
    hnext_kernel<<<(B_SZ * 256 * HW) / 256, 256>>>(T, sc2, sh2, out);
}

// round 4
// speedup vs baseline: 1.7746x; 1.7746x over previous
#include <cuda_runtime.h>
#include <cuda_bf16.h>
#include <stdint.h>
#include <math.h>

#define HW 16384           // 128*128
#define B_SZ 4
#define IMG_W 128
#define EPS 1e-5f

// ---------------- scratch (device globals; no allocation allowed) ----------------
__device__ __align__(256) float g_buf[201326592];
__device__ __align__(256) float g_red1[64];
__device__ __align__(256) float g_red2[64];
__device__ __align__(256) float g_scale1[1024];
__device__ __align__(256) float g_shift1[1024];
__device__ __align__(256) float g_scale2[1024];
__device__ __align__(256) float g_shift2[1024];

#define OFF_P     ((size_t)0)
#define OFF_XN    ((size_t)16777216)
#define OFF_QKV   ((size_t)33554432)
#define OFF_AO    ((size_t)83886080)
#define OFF_AM    ((size_t)100663296)
#define OFF_T     ((size_t)117440512)
#define OFF_GATES ((size_t)134217728)

#define NWELEM 606208
__device__ __align__(256) __nv_bfloat16 g_whi[NWELEM];
__device__ __align__(256) __nv_bfloat16 g_wlo[NWELEM];
#define WOFF_INPJ  0
#define WOFF_QKV   81920
#define WOFF_PROJ  278528
#define WOFF_GATES 344064

// ---------------- PTX helpers (arch-GENERIC: ldmatrix + mma.sync only) ----------------
__device__ __forceinline__ uint32_t smem_u32(const void* p) {
    uint32_t a;
    asm("{ .reg .u64 t; cvta.to.shared.u64 t, %1; cvt.u32.u64 %0, t; }" : "=r"(a) : "l"(p));
    return a;
}
__device__ __forceinline__ void ldmx4(uint32_t* r, uint32_t a) {
    asm volatile("ldmatrix.sync.aligned.m8n8.x4.shared.b16 {%0,%1,%2,%3}, [%4];"
        : "=r"(r[0]), "=r"(r[1]), "=r"(r[2]), "=r"(r[3]) : "r"(a));
}
__device__ __forceinline__ void ldmx4t(uint32_t* r, uint32_t a) {
    asm volatile("ldmatrix.sync.aligned.m8n8.x4.trans.shared.b16 {%0,%1,%2,%3}, [%4];"
        : "=r"(r[0]), "=r"(r[1]), "=r"(r[2]), "=r"(r[3]) : "r"(a));
}
__device__ __forceinline__ void mma16816(float* d, const uint32_t* a, uint32_t b0, uint32_t b1) {
    asm volatile(
        "mma.sync.aligned.m16n8k16.row.col.f32.bf16.bf16.f32 "
        "{%0,%1,%2,%3}, {%4,%5,%6,%7}, {%8,%9}, {%0,%1,%2,%3};"
        : "+f"(d[0]), "+f"(d[1]), "+f"(d[2]), "+f"(d[3])
        : "r"(a[0]), "r"(a[1]), "r"(a[2]), "r"(a[3]), "r"(b0), "r"(b1));
}
__device__ __forceinline__ void sts128(uint32_t a, uint4 v) {
    asm volatile("st.shared.v4.b32 [%0], {%1,%2,%3,%4};"
                 :: "r"(a), "r"(v.x), "r"(v.y), "r"(v.z), "r"(v.w) : "memory");
}
__device__ __forceinline__ uint32_t pack2(float a, float b) {
    __nv_bfloat162 t = __floats2bfloat162_rn(a, b);
    return *reinterpret_cast<uint32_t*>(&t);
}

// ---------------- utility kernels ----------------
__global__ void zero_red_kernel() {
    int i = threadIdx.x;
    if (i < 64) { g_red1[i] = 0.f; g_red2[i] = 0.f; }
}

__global__ void wconv_kernel(const float* __restrict__ src, int off, int n) {
    int i = blockIdx.x * 256 + threadIdx.x;
    if (i < n) {
        float f = src[i];
        __nv_bfloat16 hi = __float2bfloat16_rn(f);
        g_whi[off + i] = hi;
        g_wlo[off + i] = __float2bfloat16_rn(f - __bfloat162float(hi));
    }
}

// ---------------- mma.sync split-bf16 GEMM ----------------
// Y[b](M x HW) = W(M x K) @ X[b](K x HW) + bias, fp32 io, bf16x3 compute.
// MODE 0: X split (x:64ch then h:256ch)   [in_proj]
// MODE 1: X0 at b*K*HW                    [qkv, proj]
// MODE 2: MODE1 + per-(b,k) affine on B   [gates, GroupNorm fused]
#define BM 128
#define BN 128
#define BKT 32
#define APITCH 40    // bf16 elems per A smem row (32 + 8 pad)
#define BPITCH 136   // bf16 elems per B smem row (128 + 8 pad)
#define S_AH 0
#define S_AL 10240
#define S_BH 20480
#define S_BL 29184
#define S_STAGE 37888
#define GEMM_SMEM (2 * S_STAGE)

template<int MODE>
__global__ void __launch_bounds__(256, 1) gemm_mma(
    const __nv_bfloat16* __restrict__ Whi, const __nv_bfloat16* __restrict__ Wlo,
    const float* __restrict__ bias,
    const float* __restrict__ X0, const float* __restrict__ X1,
    const float* __restrict__ scl, const float* __restrict__ shf,
    float* __restrict__ Y, int M, int K)
{
    extern __shared__ char smc[];
    const uint32_t sb = smem_u32(smc);
    const int tid = threadIdx.x, lane = tid & 31, wid = tid >> 5;
    const int b = blockIdx.z;
    const int n0 = blockIdx.x * BN;
    const int m0 = blockIdx.y * BM;
    const int nk = K / BKT;

    // staging assignment
    const int am   = tid >> 1;            // A row (0..127)
    const int aseg = (tid & 1) << 4;      // A col seg (0 or 16 bf16)
    const int bk   = tid >> 3;            // B row k (0..31)
    const int bseg = (tid & 7) << 4;      // B col seg (16 floats)

    // warp tile
    const int wm = (wid >> 2) * 64;
    const int wn = (wid & 3) * 32;

    uint4 rA[4];        // A hi(2) + lo(2) staged regs
    float rB[16];       // B staged fp32

    float acc[4][4][4];
    #pragma unroll
    for (int i = 0; i < 4; i++)
        #pragma unroll
        for (int j = 0; j < 4; j++)
            #pragma unroll
            for (int q = 0; q < 4; q++) acc[i][j][q] = 0.f;

    auto ldg_tile = [&](int kt) {
        const int k0 = kt * BKT;
        const __nv_bfloat16* ph = Whi + (size_t)(m0 + am) * K + k0 + aseg;
        const __nv_bfloat16* pl = Wlo + (size_t)(m0 + am) * K + k0 + aseg;
        rA[0] = ((const uint4*)ph)[0]; rA[1] = ((const uint4*)ph)[1];
        rA[2] = ((const uint4*)pl)[0]; rA[3] = ((const uint4*)pl)[1];
        const int kk = k0 + bk;
        const float* src;
        if (MODE == 0)
            src = (kk < 64) ? (X0 + ((size_t)b * 64 + kk) * HW)
                            : (X1 + ((size_t)b * 256 + (kk - 64)) * HW);
        else
            src = X0 + ((size_t)b * K + kk) * HW;
        const float* p = src + n0 + bseg;
        *(float4*)(rB + 0)  = ((const float4*)p)[0];
        *(float4*)(rB + 4)  = ((const float4*)p)[1];
        *(float4*)(rB + 8)  = ((const float4*)p)[2];
        *(float4*)(rB + 12) = ((const float4*)p)[3];
        if (MODE == 2) {
            float s = scl[b * K + kk], t = shf[b * K + kk];
            #pragma unroll
            for (int i = 0; i < 16; i++) rB[i] = rB[i] * s + t;
        }
    };

    auto sts_tile = [&](int st) {
        const uint32_t base = sb + st * S_STAGE;
        const uint32_t ao = base + (am * APITCH + aseg) * 2;
        sts128(ao + S_AH, rA[0]); sts128(ao + S_AH + 16, rA[1]);
        sts128(ao + S_AL, rA[2]); sts128(ao + S_AL + 16, rA[3]);
        uint4 H0, H1, L0, L1;
        float hf[16];
        #pragma unroll
        for (int i = 0; i < 16; i++)
            hf[i] = __bfloat162float(__float2bfloat16_rn(rB[i]));
        H0.x = pack2(rB[0], rB[1]);   H0.y = pack2(rB[2], rB[3]);
        H0.z = pack2(rB[4], rB[5]);   H0.w = pack2(rB[6], rB[7]);
        H1.x = pack2(rB[8], rB[9]);   H1.y = pack2(rB[10], rB[11]);
        H1.z = pack2(rB[12], rB[13]); H1.w = pack2(rB[14], rB[15]);
        L0.x = pack2(rB[0]-hf[0], rB[1]-hf[1]);   L0.y = pack2(rB[2]-hf[2], rB[3]-hf[3]);
        L0.z = pack2(rB[4]-hf[4], rB[5]-hf[5]);   L0.w = pack2(rB[6]-hf[6], rB[7]-hf[7]);
        L1.x = pack2(rB[8]-hf[8], rB[9]-hf[9]);   L1.y = pack2(rB[10]-hf[10], rB[11]-hf[11]);
        L1.z = pack2(rB[12]-hf[12], rB[13]-hf[13]); L1.w = pack2(rB[14]-hf[14], rB[15]-hf[15]);
        const uint32_t bo = base + (bk * BPITCH + bseg) * 2;
        sts128(bo + S_BH, H0); sts128(bo + S_BH + 16, H1);
        sts128(bo + S_BL, L0); sts128(bo + S_BL + 16, L1);
    };

    ldg_tile(0);
    sts_tile(0);
    __syncthreads();

    for (int kt = 0; kt < nk; kt++) {
        const bool more = (kt + 1 < nk);
        if (more) ldg_tile(kt + 1);
        const uint32_t base = sb + (kt & 1) * S_STAGE;

        #pragma unroll
        for (int ks = 0; ks < 2; ks++) {
            // A fragments
            const uint32_t arow = (uint32_t)(lane & 15);
            const uint32_t acol = (uint32_t)(ks * 16 + (lane >> 4) * 8);
            uint32_t ah[4][4], al[4][4];
            #pragma unroll
            for (int mi = 0; mi < 4; mi++) {
                uint32_t off = ((wm + mi * 16 + arow) * APITCH + acol) * 2;
                ldmx4(ah[mi], base + S_AH + off);
                ldmx4(al[mi], base + S_AL + off);
            }
            // B fragments (trans)
            const uint32_t brow = (uint32_t)(ks * 16 + (lane & 7) + ((lane >> 3) & 1) * 8);
            const uint32_t bcol = (uint32_t)(wn + (lane >> 4) * 8);
            uint32_t bh[2][4], bl[2][4];
            #pragma unroll
            for (int nj = 0; nj < 2; nj++) {
                uint32_t off = (brow * BPITCH + bcol + nj * 16) * 2;
                ldmx4t(bh[nj], base + S_BH + off);
                ldmx4t(bl[nj], base + S_BL + off);
            }
            #pragma unroll
            for (int mi = 0; mi < 4; mi++)
                #pragma unroll
                for (int n = 0; n < 4; n++) {
                    const int j = n >> 1, s = (n & 1) * 2;
                    mma16816(acc[mi][n], ah[mi], bh[j][s], bh[j][s + 1]);
                    mma16816(acc[mi][n], ah[mi], bl[j][s], bl[j][s + 1]);
                    mma16816(acc[mi][n], al[mi], bh[j][s], bh[j][s + 1]);
                }
        }
        if (more) sts_tile((kt + 1) & 1);
        __syncthreads();
    }

    // epilogue: D frag (d0,d1: row lane/4, cols (lane%4)*2; d2,d3: row+8)
    #pragma unroll
    for (int mi = 0; mi < 4; mi++) {
        const int mrow = m0 + wm + mi * 16 + (lane >> 2);
        const float b0v = __ldg(bias + mrow);
        const float b1v = __ldg(bias + mrow + 8);
        float* y0 = Y + ((size_t)b * M + mrow) * HW;
        float* y1 = Y + ((size_t)b * M + mrow + 8) * HW;
        #pragma unroll
        for (int n = 0; n < 4; n++) {
            const int nc = n0 + wn + n * 8 + (lane & 3) * 2;
            float2 v0 = make_float2(acc[mi][n][0] + b0v, acc[mi][n][1] + b0v);
            float2 v1 = make_float2(acc[mi][n][2] + b1v, acc[mi][n][3] + b1v);
            *(float2*)(y0 + nc) = v0;
            *(float2*)(y1 + nc) = v1;
        }
    }
}

// ---------------- per-pixel LayerNorm over 256 channels ----------------
__global__ void __launch_bounds__(256) ln_kernel(
    const float* __restrict__ P, const float* __restrict__ g,
    const float* __restrict__ be, float* __restrict__ XN)
{
    int idx = blockIdx.x * 256 + threadIdx.x;
    int b = idx >> 14;
    int p = idx & 16383;
    const float* base = P + (size_t)b * 256 * HW + p;
    float s = 0.f, ss = 0.f;
    for (int c = 0; c < 256; c++) {
        float v = base[(size_t)c * HW];
        s += v; ss += v * v;
    }
    float mu = s * (1.f / 256.f);
    float var = ss * (1.f / 256.f) - mu * mu;
    float rstd = rsqrtf(var + EPS);
    float* ob = XN + (size_t)b * 256 * HW + p;
    for (int c = 0; c < 256; c++) {
        float v = base[(size_t)c * HW];
        ob[(size_t)c * HW] = (v - mu) * rstd * __ldg(&g[c]) + __ldg(&be[c]);
    }
}

// ---------------- window attention (4x4 windows, 8 heads, hd=32) ----------------
__global__ void __launch_bounds__(128) attn_kernel(
    const float* __restrict__ QKV, float* __restrict__ AO)
{
    __shared__ float sq[8 * 512];
    __shared__ float sk[8 * 512];
    __shared__ float sv[8 * 512];

    const int wc = blockIdx.x, wr = blockIdx.y, b = blockIdx.z;
    const int tid = threadIdx.x;
    const float* base = QKV + (size_t)b * 768 * HW;

    for (int e = tid; e < 3 * 4096; e += 128) {
        int t  = e & 15;
        int d  = (e >> 4) & 31;
        int hh = (e >> 9) & 7;
        int s  = e >> 12;
        int pix = (wr * 4 + (t >> 2)) * IMG_W + wc * 4 + (t & 3);
        float v = base[((size_t)(s * 256 + hh * 32 + d)) * HW + pix];
        float* sm = (s == 0) ? sq : (s == 1) ? sk : sv;
        sm[hh * 512 + d * 16 + t] = v;
    }
    __syncthreads();

    const int h  = tid >> 4;
    const int qt = tid & 15;
    const float* qb = sq + h * 512;
    const float* kb = sk + h * 512;
    const float* vb = sv + h * 512;

    float s[16];
    #pragma unroll
    for (int kt = 0; kt < 16; kt++) s[kt] = 0.f;
    #pragma unroll 4
    for (int d = 0; d < 32; d++) {
        float qv = qb[d * 16 + qt];
        #pragma unroll
        for (int kt = 0; kt < 16; kt++)
            s[kt] = fmaf(qv, kb[d * 16 + kt], s[kt]);
    }
    const float sc = 0.17677669529663687f;
    float mx = -1e30f;
    #pragma unroll
    for (int kt = 0; kt < 16; kt++) { s[kt] *= sc; mx = fmaxf(mx, s[kt]); }
    float den = 0.f;
    #pragma unroll
    for (int kt = 0; kt < 16; kt++) { s[kt] = __expf(s[kt] - mx); den += s[kt]; }
    float rden = 1.f / den;

    int pix = (wr * 4 + (qt >> 2)) * IMG_W + wc * 4 + (qt & 3);
    float* ob = AO + (size_t)b * 256 * HW + pix;
    #pragma unroll 4
    for (int d = 0; d < 32; d++) {
        float o = 0.f;
        #pragma unroll
        for (int kt = 0; kt < 16; kt++)
            o = fmaf(s[kt], vb[d * 16 + kt], o);
        ob[(size_t)(h * 32 + d) * HW] = o * rden;
    }
}

// ---------------- block reduction helper ----------------
__device__ __forceinline__ void block_sum2(float& s, float& ss) {
    __shared__ float sm1[8], sm2[8];
    #pragma unroll
    for (int o = 16; o > 0; o >>= 1) {
        s  += __shfl_xor_sync(0xffffffff, s, o);
        ss += __shfl_xor_sync(0xffffffff, ss, o);
    }
    int w = threadIdx.x >> 5, l = threadIdx.x & 31;
    if (l == 0) { sm1[w] = s; sm2[w] = ss; }
    __syncthreads();
    if (threadIdx.x < 32) {
        s  = (l < 8) ? sm1[l] : 0.f;
        ss = (l < 8) ? sm2[l] : 0.f;
        #pragma unroll
        for (int o = 4; o > 0; o >>= 1) {
            s  += __shfl_xor_sync(0xffffffff, s, o);
            ss += __shfl_xor_sync(0xffffffff, ss, o);
        }
    }
}

// ---------------- GroupNorm stage 1: reduce am ----------------
__global__ void __launch_bounds__(256) gn_reduce_kernel(const float* __restrict__ X) {
    int grp = blockIdx.y;
    const float* base = X + (size_t)grp * 32 * HW;
    int start = blockIdx.x * 32768 + threadIdx.x;
    float s = 0.f, ss = 0.f;
    #pragma unroll 4
    for (int i = 0; i < 128; i++) {
        float v = base[start + i * 256];
        s += v; ss += v * v;
    }
    block_sum2(s, ss);
    if (threadIdx.x == 0) {
        atomicAdd(&g_red1[grp * 2 + 0], s);
        atomicAdd(&g_red1[grp * 2 + 1], ss);
    }
}

__global__ void gn_finalize_kernel(const float* __restrict__ red,
                                   const float* __restrict__ g, const float* __restrict__ be,
                                   float* __restrict__ scale, float* __restrict__ shift)
{
    int i = blockIdx.x * 256 + threadIdx.x;
    int c = i & 255;
    int grp = (i >> 8) * 8 + (c >> 5);
    const float invN = 1.f / 524288.f;
    float mu = red[grp * 2 + 0] * invN;
    float var = red[grp * 2 + 1] * invN - mu * mu;
    float rstd = rsqrtf(var + EPS);
    float gg = g[c];
    scale[i] = gg * rstd;
    shift[i] = be[c] - mu * rstd * gg;
}

// ---------------- LSTM elementwise + stats for second GroupNorm ----------------
__global__ void __launch_bounds__(256) lstm_kernel(
    const float* __restrict__ G, const float* __restrict__ Cin,
    float* __restrict__ Cout, float* __restrict__ T)
{
    size_t idx = (size_t)blockIdx.x * 256 + threadIdx.x;
    int b = (int)(idx >> 22);
    int rem = (int)(idx & 4194303);
    int c = rem >> 14;
    size_t gbase = (size_t)b * 1024 * HW + rem;

    float i_ = G[gbase];
    float f_ = G[gbase + (size_t)256 * HW];
    float o_ = G[gbase + (size_t)512 * HW];
    float g_ = G[gbase + (size_t)768 * HW];
    i_ = 1.f / (1.f + __expf(-i_));
    f_ = 1.f / (1.f + __expf(-f_));
    o_ = 1.f / (1.f + __expf(-o_));
    g_ = tanhf(g_);
    float cn = f_ * Cin[idx] + i_ * g_;
    Cout[idx] = cn;
    float t = o_ * tanhf(cn);
    T[idx] = t;

    float s = t, ss = t * t;
    block_sum2(s, ss);
    if (threadIdx.x == 0) {
        int grp = b * 8 + (c >> 5);
        atomicAdd(&g_red2[grp * 2 + 0], s);
        atomicAdd(&g_red2[grp * 2 + 1], ss);
    }
}

__global__ void __launch_bounds__(256) hnext_kernel(
    const float* __restrict__ T, const float* __restrict__ scale,
    const float* __restrict__ shift, float* __restrict__ Hout)
{
    size_t idx = (size_t)blockIdx.x * 256 + threadIdx.x;
    int b = (int)(idx >> 22);
    int c = (int)((idx >> 14) & 255);
    int sidx = b * 256 + c;
    Hout[idx] = T[idx] * __ldg(&scale[sidx]) + __ldg(&shift[sidx]);
}

// ---------------- launcher ----------------
extern "C" void kernel_launch(void* const* d_in, const int* in_sizes, int n_in,
                              void* d_out, int out_size)
{
    const float* x         = (const float*)d_in[0];
    const float* h         = (const float*)d_in[1];
    const float* c         = (const float*)d_in[2];
    const float* in_proj_w = (const float*)d_in[3];
    const float* in_proj_b = (const float*)d_in[4];
    const float* ln_g      = (const float*)d_in[5];
    const float* ln_b      = (const float*)d_in[6];
    const float* qkv_w     = (const float*)d_in[7];
    const float* qkv_b     = (const float*)d_in[8];
    const float* proj_w    = (const float*)d_in[9];
    const float* proj_b    = (const float*)d_in[10];
    const float* gates_w   = (const float*)d_in[11];
    const float* gates_b   = (const float*)d_in[12];
    const float* gn_g      = (const float*)d_in[13];
    const float* gn_b      = (const float*)d_in[14];
    float* out = (float*)d_out;

    float *buf, *red1, *red2, *sc1, *sh1, *sc2, *sh2;
    __nv_bfloat16 *whi, *wlo;
    cudaGetSymbolAddress((void**)&buf,  g_buf);
    cudaGetSymbolAddress((void**)&red1, g_red1);
    cudaGetSymbolAddress((void**)&red2, g_red2);
    cudaGetSymbolAddress((void**)&sc1,  g_scale1);
    cudaGetSymbolAddress((void**)&sh1,  g_shift1);
    cudaGetSymbolAddress((void**)&sc2,  g_scale2);
    cudaGetSymbolAddress((void**)&sh2,  g_shift2);
    cudaGetSymbolAddress((void**)&whi,  g_whi);
    cudaGetSymbolAddress((void**)&wlo,  g_wlo);

    float* P     = buf + OFF_P;
    float* XN    = buf + OFF_XN;
    float* QKV   = buf + OFF_QKV;
    float* AO    = buf + OFF_AO;
    float* AM    = buf + OFF_AM;
    float* T     = buf + OFF_T;
    float* GATES = buf + OFF_GATES;

    cudaFuncSetAttribute(gemm_mma<0>, cudaFuncAttributeMaxDynamicSharedMemorySize, GEMM_SMEM);
    cudaFuncSetAttribute(gemm_mma<1>, cudaFuncAttributeMaxDynamicSharedMemorySize, GEMM_SMEM);
    cudaFuncSetAttribute(gemm_mma<2>, cudaFuncAttributeMaxDynamicSharedMemorySize, GEMM_SMEM);

    zero_red_kernel<<<1, 64>>>();

    // split weights fp32 -> bf16 hi/lo (device globals)
    wconv_kernel<<<(81920  + 255) / 256, 256>>>(in_proj_w, WOFF_INPJ, 81920);
    wconv_kernel<<<(196608 + 255) / 256, 256>>>(qkv_w,     WOFF_QKV, 196608);
    wconv_kernel<<<(65536  + 255) / 256, 256>>>(proj_w,    WOFF_PROJ, 65536);
    wconv_kernel<<<(262144 + 255) / 256, 256>>>(gates_w,   WOFF_GATES, 262144);

    // 1) in_proj: P = W(256x320) @ [x;h] + b
    gemm_mma<0><<<dim3(HW / BN, 256 / BM, B_SZ), 256, GEMM_SMEM>>>(
        whi + WOFF_INPJ, wlo + WOFF_INPJ, in_proj_b, x, h, nullptr, nullptr, P, 256, 320);

    // 2) LayerNorm per pixel
    ln_kernel<<<(B_SZ * HW) / 256, 256>>>(P, ln_g, ln_b, XN);

    // 3) qkv
    gemm_mma<1><<<dim3(HW / BN, 768 / BM, B_SZ), 256, GEMM_SMEM>>>(
        whi + WOFF_QKV, wlo + WOFF_QKV, qkv_b, XN, nullptr, nullptr, nullptr, QKV, 768, 256);

    // 4) window attention
    attn_kernel<<<dim3(32, 32, B_SZ), 128>>>(QKV, AO);

    // 5) proj
    gemm_mma<1><<<dim3(HW / BN, 256 / BM, B_SZ), 256, GEMM_SMEM>>>(
        whi + WOFF_PROJ, wlo + WOFF_PROJ, proj_b, AO, nullptr, nullptr, nullptr, AM, 256, 256);

    // 6) GroupNorm(am) stats
    gn_reduce_kernel<<<dim3(16, 32), 256>>>(AM);
    gn_finalize_kernel<<<4, 256>>>(red1, gn_g, gn_b, sc1, sh1);

    // 7) gates (GroupNorm fused via affine on B)
    gemm_mma<2><<<dim3(HW / BN, 1024 / BM, B_SZ), 256, GEMM_SMEM>>>(
        whi + WOFF_GATES, wlo + WOFF_GATES, gates_b, AM, nullptr, sc1, sh1, GATES, 1024, 256);

    // 8) LSTM elementwise: cnext -> out[2nd half], t -> T, stats -> red2
    lstm_kernel<<<(B_SZ * 256 * HW) / 256, 256>>>(
        GATES, c, out + (size_t)B_SZ * 256 * HW, T);

    // 9) hnext = GroupNorm(t) -> out[1st half]
    gn_finalize_kernel<<<4, 256>>>(red2, gn_g, gn_b, sc2, sh2);
    hnext_kernel<<<(B_SZ * 256 * HW) / 256, 256>>>(T, sc2, sh2, out);
}